// round 2
// baseline (speedup 1.0000x reference)
#include <cuda_runtime.h>
#include <math.h>

#define B_  4096
#define E_  64
#define D_  1024
#define BM  32
#define KC  32
#define NC  64
#define NBLK (B_ / BM)   // 128

typedef unsigned long long ull;

// Scratch (allocation-free rule: __device__ globals)
__device__ float g_sinv[D_];
__device__ float g_esT[D_ * E_];  // transposed scaled experts: [d][e] = sinv[d]*ek[e][d]
__device__ float g_en[E_];        // sum_d sinv * ek^2

union F2U { ull u; float2 f; };

static __device__ __forceinline__ ull fma2(ull a, ull b, ull c) {
    ull d;
    asm("fma.rn.f32x2 %0, %1, %2, %3;" : "=l"(d) : "l"(a), "l"(b), "l"(c));
    return d;
}

// ---------------------------------------------------------------------------
// Prep: sigma_inv, transposed scaled experts, expert norms.
// ---------------------------------------------------------------------------
__global__ __launch_bounds__(256) void prep_kernel(const float* __restrict__ ek,
                                                   const float* __restrict__ ls) {
    int e = blockIdx.x;
    int tid = threadIdx.x;
    float acc = 0.f;
    for (int d = tid; d < D_; d += 256) {
        float s = __expf(-ls[d]);
        if (e == 0) g_sinv[d] = s;
        float v = ek[e * D_ + d];
        float sv = s * v;
        g_esT[d * E_ + e] = sv;
        acc += sv * v;
    }
    __shared__ float red[8];
    #pragma unroll
    for (int o = 16; o > 0; o >>= 1) acc += __shfl_down_sync(0xffffffffu, acc, o);
    if ((tid & 31) == 0) red[tid >> 5] = acc;
    __syncthreads();
    if (tid == 0) {
        float s = 0.f;
        #pragma unroll
        for (int i = 0; i < 8; i++) s += red[i];
        g_en[e] = s;
    }
}

// ---------------------------------------------------------------------------
// Fused main kernel with f32x2-packed FMAs.
// ---------------------------------------------------------------------------
#define OFF_ZDUP   0
#define OFF_ET     (32 * 34 * 8)              // 8704
#define OFF_WDUP   17408                       // regionA = max(17408) bytes
#define OFF_ZN     (OFF_WDUP + 64 * 34 * 8)    // + 17408
#define SMEM_BYTES (OFF_ZN + (32 + 64) * 4)

__global__ __launch_bounds__(256) void MahalanobisSimilarity_71502615544487_kernel(
        const float* __restrict__ z,
        const float* __restrict__ ek,
        float* __restrict__ out_sim,   // [B, E]
        float* __restrict__ out_w)     // [B, D]
{
    __shared__ __align__(16) unsigned char smem[SMEM_BYTES];

    float2* sZdup = (float2*)(smem + OFF_ZDUP);   // [k][34] slots, slot m = {z,z}
    float2* sEt   = (float2*)(smem + OFF_ET);     // [k][34] slots, slot p = {es2p, es2p+1}
    float*  sW    = (float*)(smem + OFF_ZDUP);    // [m][68] similarity (reuses regionA)
    float2* sB    = (float2*)(smem + OFF_ZDUP);   // [e][34] slots (phase 3, reuses regionA)
    float2* sWdup = (float2*)(smem + OFF_WDUP);   // [e][34] slots, slot m = {w,w}
    float*  s_zn  = (float*)(smem + OFF_ZN);
    float*  s_en  = s_zn + 32;

    const int tid = threadIdx.x;
    const int r0  = blockIdx.x * BM;
    const int tx  = tid & 15;
    const int ty  = tid >> 4;

    if (tid < E_) s_en[tid] = g_en[tid];

    // ---- Phase 0: zn[m] = sum_d sinv * z^2 (8 threads per row) ----
    {
        int row = tid >> 3;
        int l8  = tid & 7;
        const float* zr = z + (size_t)(r0 + row) * D_;
        float acc = 0.f;
        for (int k = l8 * 4; k < D_; k += 32) {
            float4 v = *(const float4*)(zr + k);
            float4 s = *(const float4*)(g_sinv + k);
            acc += s.x * v.x * v.x + s.y * v.y * v.y
                 + s.z * v.z * v.z + s.w * v.w * v.w;
        }
        acc += __shfl_down_sync(0xffffffffu, acc, 4, 8);
        acc += __shfl_down_sync(0xffffffffu, acc, 2, 8);
        acc += __shfl_down_sync(0xffffffffu, acc, 1, 8);
        if (l8 == 0) s_zn[row] = acc;
    }

    // ---- Phase 1: dot[m][e] = z_m . es_e via f32x2 (M=32,N=64,K=1024) ----
    ull acc00 = 0, acc01 = 0, acc10 = 0, acc11 = 0;

    const int stage_m  = tid >> 3;
    const int stage_k4 = (tid & 7) << 2;
    const int et_k     = tid >> 3;
    const int et_c4    = tid & 7;

    for (int kc = 0; kc < D_; kc += KC) {
        __syncthreads();
        {   // stage sZdup: one float4 of z per thread -> 4 duplicated float2 slots
            float4 v = *(const float4*)(z + (size_t)(r0 + stage_m) * D_ + kc + stage_k4);
            sZdup[(stage_k4 + 0) * 34 + stage_m] = make_float2(v.x, v.x);
            sZdup[(stage_k4 + 1) * 34 + stage_m] = make_float2(v.y, v.y);
            sZdup[(stage_k4 + 2) * 34 + stage_m] = make_float2(v.z, v.z);
            sZdup[(stage_k4 + 3) * 34 + stage_m] = make_float2(v.w, v.w);
        }
        {   // stage sEt: rows of g_esT copied straight (pairs are natural)
            #pragma unroll
            for (int i = 0; i < 2; i++) {
                int c4 = et_c4 + 8 * i;
                float4 v = *(const float4*)(g_esT + (size_t)(kc + et_k) * E_ + c4 * 4);
                *(float4*)(&sEt[et_k * 34 + c4 * 2]) = v;
            }
        }
        __syncthreads();
        #pragma unroll
        for (int k = 0; k < KC; k++) {
            float4 a4 = *(const float4*)(&sZdup[k * 34 + 2 * ty]);
            F2U a0; a0.f = make_float2(a4.x, a4.y);
            F2U a1; a1.f = make_float2(a4.z, a4.w);
            ull b0 = *(const ull*)(&sEt[k * 34 + tx]);
            ull b1 = *(const ull*)(&sEt[k * 34 + tx + 16]);
            acc00 = fma2(a0.u, b0, acc00);
            acc01 = fma2(a0.u, b1, acc01);
            acc10 = fma2(a1.u, b0, acc10);
            acc11 = fma2(a1.u, b1, acc11);
        }
    }
    __syncthreads();

    // ---- Phase 2a: similarity = 1/(1+dist) -> sW + out_sim ----
    {
        ull accs[2][2] = {{acc00, acc01}, {acc10, acc11}};
        #pragma unroll
        for (int i = 0; i < 2; i++) {
            int m = 2 * ty + i;
            float zn = s_zn[m];
            #pragma unroll
            for (int j = 0; j < 2; j++) {
                int e0 = 2 * (tx + 16 * j);
                F2U d; d.u = accs[i][j];
                float dist0 = zn + s_en[e0]     - 2.f * d.f.x;
                float dist1 = zn + s_en[e0 + 1] - 2.f * d.f.y;
                float sim0 = 1.f / (1.f + dist0);
                float sim1 = 1.f / (1.f + dist1);
                sW[m * 68 + e0]     = sim0;
                sW[m * 68 + e0 + 1] = sim1;
                *(float2*)(out_sim + (size_t)(r0 + m) * E_ + e0) = make_float2(sim0, sim1);
            }
        }
    }
    __syncthreads();

    // ---- Phase 2b: softmax over E per row; write duplicated weights [e][m] ----
    {
        int w = tid >> 5, lane = tid & 31;
        #pragma unroll
        for (int rr = 0; rr < 4; rr++) {
            int m = w * 4 + rr;
            float v0 = sW[m * 68 + lane];
            float v1 = sW[m * 68 + lane + 32];
            float mx = fmaxf(v0, v1);
            #pragma unroll
            for (int o = 16; o; o >>= 1)
                mx = fmaxf(mx, __shfl_xor_sync(0xffffffffu, mx, o));
            float e0 = __expf(v0 - mx);
            float e1 = __expf(v1 - mx);
            float s = e0 + e1;
            #pragma unroll
            for (int o = 16; o; o >>= 1)
                s += __shfl_xor_sync(0xffffffffu, s, o);
            float inv = 1.f / s;
            float w0 = e0 * inv, w1 = e1 * inv;
            sWdup[lane * 34 + m]        = make_float2(w0, w0);
            sWdup[(lane + 32) * 34 + m] = make_float2(w1, w1);
        }
    }
    __syncthreads();

    // ---- Phase 3: out_w[m][d] = sum_e W[m][e] * ek[e][d], chunks of NC=64 ----
    const int b_e = tid >> 2;
    const int b_q = tid & 3;
    for (int dc = 0; dc < D_; dc += NC) {
        #pragma unroll
        for (int j = 0; j < 4; j++) {
            int c4 = b_q + 4 * j;
            float4 v = *(const float4*)(ek + (size_t)b_e * D_ + dc + c4 * 4);
            *(float4*)(&sB[b_e * 34 + c4 * 2]) = v;
        }
        __syncthreads();
        ull o00 = 0, o01 = 0, o10 = 0, o11 = 0;
        #pragma unroll 16
        for (int e = 0; e < E_; e++) {
            float4 a4 = *(const float4*)(&sWdup[e * 34 + 2 * ty]);
            F2U a0; a0.f = make_float2(a4.x, a4.y);
            F2U a1; a1.f = make_float2(a4.z, a4.w);
            ull b0 = *(const ull*)(&sB[e * 34 + tx]);
            ull b1 = *(const ull*)(&sB[e * 34 + tx + 16]);
            o00 = fma2(a0.u, b0, o00);
            o01 = fma2(a0.u, b1, o01);
            o10 = fma2(a1.u, b0, o10);
            o11 = fma2(a1.u, b1, o11);
        }
        {
            int m0 = 2 * ty, m1 = m0 + 1;
            int d0 = dc + 2 * tx, d1 = dc + 2 * (tx + 16);
            F2U t;
            t.u = o00; *(float2*)(out_w + (size_t)(r0 + m0) * D_ + d0) = t.f;
            t.u = o01; *(float2*)(out_w + (size_t)(r0 + m0) * D_ + d1) = t.f;
            t.u = o10; *(float2*)(out_w + (size_t)(r0 + m1) * D_ + d0) = t.f;
            t.u = o11; *(float2*)(out_w + (size_t)(r0 + m1) * D_ + d1) = t.f;
        }
        __syncthreads();
    }
}

// ---------------------------------------------------------------------------
extern "C" void kernel_launch(void* const* d_in, const int* in_sizes, int n_in,
                              void* d_out, int out_size) {
    const float* z  = (const float*)d_in[0];   // [B, D]
    const float* ek = (const float*)d_in[1];   // [E, D]
    const float* ls = (const float*)d_in[2];   // [D]
    float* out = (float*)d_out;
    float* out_sim = out;                      // [B, E]
    float* out_w   = out + (size_t)B_ * E_;    // [B, D]

    prep_kernel<<<E_, 256>>>(ek, ls);
    MahalanobisSimilarity_71502615544487_kernel<<<NBLK, 256>>>(z, ek, out_sim, out_w);
}

// round 3
// speedup vs baseline: 1.3404x; 1.3404x over previous
#include <cuda_runtime.h>
#include <math.h>

#define B_      4096
#define E_      64
#define D_      1024
#define KS      64            // K-chunk for dist GEMM
#define NCHUNK  (D_ / KS)     // 16

typedef unsigned long long ull;

// -------- scratch (__device__ globals; no allocs allowed) --------
__device__ float g_sinv[D_];
__device__ float g_esT[D_ * E_];               // [d][e] = sinv[d] * ek[e][d]
__device__ float g_en[E_];                     // sum_d sinv * ek^2
__device__ float g_part[NCHUNK * B_ * E_];     // 16 MB partial dots
__device__ float g_w[B_ * E_];                 // softmax weights

union F2U { ull u; float2 f; };

static __device__ __forceinline__ ull fma2(ull a, ull b, ull c) {
    ull d;
    asm("fma.rn.f32x2 %0, %1, %2, %3;" : "=l"(d) : "l"(a), "l"(b), "l"(c));
    return d;
}
static __device__ __forceinline__ ull dup2(float v) {
    F2U t; t.f = make_float2(v, v); return t.u;
}

// ---------------------------------------------------------------------------
// K1: prep — sigma_inv, transposed scaled experts, expert norms
// ---------------------------------------------------------------------------
__global__ __launch_bounds__(256) void prep_kernel(const float* __restrict__ ek,
                                                   const float* __restrict__ ls) {
    int e = blockIdx.x;
    int tid = threadIdx.x;
    float acc = 0.f;
    for (int d = tid; d < D_; d += 256) {
        float s = __expf(-ls[d]);
        if (e == 0) g_sinv[d] = s;
        float v = ek[e * D_ + d];
        float sv = s * v;
        g_esT[d * E_ + e] = sv;
        acc += sv * v;
    }
    __shared__ float red[8];
    #pragma unroll
    for (int o = 16; o > 0; o >>= 1) acc += __shfl_down_sync(0xffffffffu, acc, o);
    if ((tid & 31) == 0) red[tid >> 5] = acc;
    __syncthreads();
    if (tid == 0) {
        float s = 0.f;
        #pragma unroll
        for (int i = 0; i < 8; i++) s += red[i];
        g_en[e] = s;
    }
}

// ---------------------------------------------------------------------------
// K2: dist partial GEMM. grid (NCHUNK, B/64). CTA: 64m x 64e x 64k chunk.
// smem: sZdup [k][64 m-slots] duplicated pairs (32KB) + sEs [k][32 e-pairs] (16KB)
// ---------------------------------------------------------------------------
__global__ __launch_bounds__(256) void k2_dist(const float* __restrict__ z) {
    __shared__ __align__(16) float2 sZdup[KS * 64];   // [k*64 + m] = {z,z}
    __shared__ __align__(16) float2 sEs[KS * 32];     // [k*32 + p] = {es,es+1}

    const int tid = threadIdx.x;
    const int kcid = blockIdx.x;
    const int kc   = kcid * KS;
    const int r0   = blockIdx.y * 64;
    const int tx   = tid & 15;         // e-quads
    const int ty   = tid >> 4;         // m-quads

    // stage z tile (duplicated, transposed [k][m])
    {
        int sm = tid >> 2, sq = tid & 3;
        const float* zr = z + (size_t)(r0 + sm) * D_ + kc + sq * 16;
        #pragma unroll
        for (int i = 0; i < 4; i++) {
            float4 v = *(const float4*)(zr + 4 * i);
            int kb = sq * 16 + 4 * i;
            sZdup[(kb + 0) * 64 + sm] = make_float2(v.x, v.x);
            sZdup[(kb + 1) * 64 + sm] = make_float2(v.y, v.y);
            sZdup[(kb + 2) * 64 + sm] = make_float2(v.z, v.z);
            sZdup[(kb + 3) * 64 + sm] = make_float2(v.w, v.w);
        }
    }
    // stage es tile (natural pairs, [k][e])
    {
        int sk = tid >> 2, sq = tid & 3;
        const float* er = g_esT + (size_t)(kc + sk) * E_ + sq * 16;
        #pragma unroll
        for (int i = 0; i < 4; i++) {
            float4 v = *(const float4*)(er + 4 * i);
            *(float4*)(&sEs[sk * 32 + sq * 8 + 2 * i]) = v;
        }
    }
    __syncthreads();

    ull acc[4][2];
    #pragma unroll
    for (int s = 0; s < 4; s++) { acc[s][0] = 0; acc[s][1] = 0; }

    #pragma unroll 4
    for (int k = 0; k < KS; k++) {
        ulonglong2 a01 = *(const ulonglong2*)(&sZdup[k * 64 + 4 * ty]);
        ulonglong2 a23 = *(const ulonglong2*)(&sZdup[k * 64 + 4 * ty + 2]);
        ulonglong2 bv  = *(const ulonglong2*)(&sEs[k * 32 + 2 * tx]);
        acc[0][0] = fma2(a01.x, bv.x, acc[0][0]);
        acc[0][1] = fma2(a01.x, bv.y, acc[0][1]);
        acc[1][0] = fma2(a01.y, bv.x, acc[1][0]);
        acc[1][1] = fma2(a01.y, bv.y, acc[1][1]);
        acc[2][0] = fma2(a23.x, bv.x, acc[2][0]);
        acc[2][1] = fma2(a23.x, bv.y, acc[2][1]);
        acc[3][0] = fma2(a23.y, bv.x, acc[3][0]);
        acc[3][1] = fma2(a23.y, bv.y, acc[3][1]);
    }

    // epilogue: float4 per m-row, coalesced
    #pragma unroll
    for (int s = 0; s < 4; s++) {
        F2U lo, hi; lo.u = acc[s][0]; hi.u = acc[s][1];
        float4 v = make_float4(lo.f.x, lo.f.y, hi.f.x, hi.f.y);
        size_t idx = ((size_t)kcid * B_ + (r0 + 4 * ty + s)) * E_ + 4 * tx;
        *(float4*)(g_part + idx) = v;
    }
}

// ---------------------------------------------------------------------------
// K3: reduce partials + zn + similarity + softmax. warp per row, grid 512.
// ---------------------------------------------------------------------------
__global__ __launch_bounds__(256) void k3_softmax(const float* __restrict__ z,
                                                  float* __restrict__ out_sim) {
    const int lane = threadIdx.x & 31;
    const int m = blockIdx.x * 8 + (threadIdx.x >> 5);

    // zn = sum_d sinv * z^2
    float zn = 0.f;
    const float* zr = z + (size_t)m * D_;
    #pragma unroll
    for (int i = 0; i < 8; i++) {
        float4 v = *(const float4*)(zr + lane * 4 + i * 128);
        float4 s = *(const float4*)(g_sinv + lane * 4 + i * 128);
        zn += s.x * v.x * v.x + s.y * v.y * v.y + s.z * v.z * v.z + s.w * v.w * v.w;
    }
    #pragma unroll
    for (int o = 16; o; o >>= 1) zn += __shfl_xor_sync(0xffffffffu, zn, o);

    // reduce partial dots: lane handles e = lane, lane+32
    float d0 = 0.f, d1 = 0.f;
    #pragma unroll
    for (int c = 0; c < NCHUNK; c++) {
        const float* p = g_part + ((size_t)c * B_ + m) * E_;
        d0 += p[lane];
        d1 += p[lane + 32];
    }

    float sim0 = 1.f / (1.f + zn + g_en[lane]      - 2.f * d0);
    float sim1 = 1.f / (1.f + zn + g_en[lane + 32] - 2.f * d1);
    out_sim[(size_t)m * E_ + lane]      = sim0;
    out_sim[(size_t)m * E_ + lane + 32] = sim1;

    float mx = fmaxf(sim0, sim1);
    #pragma unroll
    for (int o = 16; o; o >>= 1) mx = fmaxf(mx, __shfl_xor_sync(0xffffffffu, mx, o));
    float e0 = __expf(sim0 - mx), e1 = __expf(sim1 - mx);
    float s = e0 + e1;
    #pragma unroll
    for (int o = 16; o; o >>= 1) s += __shfl_xor_sync(0xffffffffu, s, o);
    float inv = 1.f / s;
    g_w[(size_t)m * E_ + lane]      = e0 * inv;
    g_w[(size_t)m * E_ + lane + 32] = e1 * inv;
}

// ---------------------------------------------------------------------------
// K4: out_w = W @ ek. grid (D/64, B/64). CTA: 64m x 64d, K = E = 64.
// smem: sWdup [e][64 m-slots] dup (32KB) + sB [e][32 d-pairs] (16KB)
// ---------------------------------------------------------------------------
__global__ __launch_bounds__(256) void k4_out(const float* __restrict__ ek,
                                              float* __restrict__ out_w) {
    __shared__ __align__(16) float2 sWdup[E_ * 64];   // [e*64 + m] = {w,w}
    __shared__ __align__(16) float2 sB[E_ * 32];      // [e*32 + p] = {ek,ek+1}

    const int tid = threadIdx.x;
    const int dc  = blockIdx.x * 64;
    const int r0  = blockIdx.y * 64;
    const int tx  = tid & 15;          // d-quads
    const int ty  = tid >> 4;          // m-quads

    // stage W tile (duplicated, transposed [e][m])
    {
        int sm = tid >> 2, sq = tid & 3;
        const float* wr = g_w + (size_t)(r0 + sm) * E_ + sq * 16;
        #pragma unroll
        for (int i = 0; i < 4; i++) {
            float4 v = *(const float4*)(wr + 4 * i);
            int eb = sq * 16 + 4 * i;
            sWdup[(eb + 0) * 64 + sm] = make_float2(v.x, v.x);
            sWdup[(eb + 1) * 64 + sm] = make_float2(v.y, v.y);
            sWdup[(eb + 2) * 64 + sm] = make_float2(v.z, v.z);
            sWdup[(eb + 3) * 64 + sm] = make_float2(v.w, v.w);
        }
    }
    // stage ek tile (natural pairs, [e][d])
    {
        int se = tid >> 2, sq = tid & 3;
        const float* er = ek + (size_t)se * D_ + dc + sq * 16;
        #pragma unroll
        for (int i = 0; i < 4; i++) {
            float4 v = *(const float4*)(er + 4 * i);
            *(float4*)(&sB[se * 32 + sq * 8 + 2 * i]) = v;
        }
    }
    __syncthreads();

    ull acc[4][2];
    #pragma unroll
    for (int s = 0; s < 4; s++) { acc[s][0] = 0; acc[s][1] = 0; }

    #pragma unroll 4
    for (int e = 0; e < E_; e++) {
        ulonglong2 a01 = *(const ulonglong2*)(&sWdup[e * 64 + 4 * ty]);
        ulonglong2 a23 = *(const ulonglong2*)(&sWdup[e * 64 + 4 * ty + 2]);
        ulonglong2 bv  = *(const ulonglong2*)(&sB[e * 32 + 2 * tx]);
        acc[0][0] = fma2(a01.x, bv.x, acc[0][0]);
        acc[0][1] = fma2(a01.x, bv.y, acc[0][1]);
        acc[1][0] = fma2(a01.y, bv.x, acc[1][0]);
        acc[1][1] = fma2(a01.y, bv.y, acc[1][1]);
        acc[2][0] = fma2(a23.x, bv.x, acc[2][0]);
        acc[2][1] = fma2(a23.x, bv.y, acc[2][1]);
        acc[3][0] = fma2(a23.y, bv.x, acc[3][0]);
        acc[3][1] = fma2(a23.y, bv.y, acc[3][1]);
    }

    #pragma unroll
    for (int s = 0; s < 4; s++) {
        F2U lo, hi; lo.u = acc[s][0]; hi.u = acc[s][1];
        float4 v = make_float4(lo.f.x, lo.f.y, hi.f.x, hi.f.y);
        *(float4*)(out_w + (size_t)(r0 + 4 * ty + s) * D_ + dc + 4 * tx) = v;
    }
}

// ---------------------------------------------------------------------------
extern "C" void kernel_launch(void* const* d_in, const int* in_sizes, int n_in,
                              void* d_out, int out_size) {
    const float* z  = (const float*)d_in[0];   // [B, D]
    const float* ek = (const float*)d_in[1];   // [E, D]
    const float* ls = (const float*)d_in[2];   // [D]
    float* out = (float*)d_out;
    float* out_sim = out;                      // [B, E]
    float* out_w   = out + (size_t)B_ * E_;    // [B, D]

    prep_kernel<<<E_, 256>>>(ek, ls);
    k2_dist<<<dim3(NCHUNK, B_ / 64), 256>>>(z);
    k3_softmax<<<B_ / 8, 256>>>(z, out_sim);
    k4_out<<<dim3(D_ / 64, B_ / 64), 256>>>(ek, out_w);
}

// round 5
// speedup vs baseline: 1.4773x; 1.1021x over previous
#include <cuda_runtime.h>
#include <math.h>

#define B_     4096
#define E_     64
#define D_     1024
#define NCHUNK 16
#define KCH    64     // k per chunk (k2)
#define KT     32     // k subtile (k2)

typedef unsigned long long ull;
union F2U { ull u; float2 f; };

// -------- scratch (__device__ globals; no allocs allowed) --------
__device__ float g_sinv[D_];
__device__ float g_es[E_ * D_];            // [e][d] = sinv[d]*ek[e][d]
__device__ float g_ekT[D_ * E_];           // [d][e] = ek[e][d]
__device__ float g_en[E_];                 // sum_d sinv*ek^2
__device__ float g_part[NCHUNK * B_ * E_]; // partial dots (16 MB)
__device__ float g_w[B_ * E_];             // softmax weights

static __device__ __forceinline__ ull fma2(ull a, ull b, ull c) {
    ull d;
    asm("fma.rn.f32x2 %0, %1, %2, %3;" : "=l"(d) : "l"(a), "l"(b), "l"(c));
    return d;
}

// ---------------------------------------------------------------------------
// K1: prep — sigma_inv, scaled experts (row-major), transposed ek, norms
// ---------------------------------------------------------------------------
__global__ __launch_bounds__(256) void prep_kernel(const float* __restrict__ ek,
                                                   const float* __restrict__ ls) {
    int e = blockIdx.x;
    int tid = threadIdx.x;
    float acc = 0.f;
    for (int d = tid; d < D_; d += 256) {
        float s = __expf(-ls[d]);
        if (e == 0) g_sinv[d] = s;
        float v = ek[e * D_ + d];
        float sv = s * v;
        g_es[e * D_ + d] = sv;
        g_ekT[d * E_ + e] = v;
        acc += sv * v;
    }
    __shared__ float red[8];
    #pragma unroll
    for (int o = 16; o > 0; o >>= 1) acc += __shfl_down_sync(0xffffffffu, acc, o);
    if ((tid & 31) == 0) red[tid >> 5] = acc;
    __syncthreads();
    if (tid == 0) {
        float s = 0.f;
        #pragma unroll
        for (int i = 0; i < 8; i++) s += red[i];
        g_en[e] = s;
    }
}

// ---------------------------------------------------------------------------
// K2: dist partial GEMM, k-paired f32x2 accumulators (no operand dup).
// grid (NCHUNK, B/128, 2). CTA: 128m x 32e x 64k. 128 threads.
// Per thread: 8m x 4e, acc lanes = {even-k sum, odd-k sum}.
// ---------------------------------------------------------------------------
__global__ __launch_bounds__(128, 4) void k2_dist(const float* __restrict__ z) {
    __shared__ __align__(16) float sZ[128][KT];  // [m][k] swizzled by 4*((m>>3)&7)
    __shared__ __align__(16) float sE[32][KT];   // [e][k] swizzled by 4*((e>>2)&7)

    const int tid = threadIdx.x;
    const int ch = blockIdx.x;
    const int r0 = blockIdx.y * 128;
    const int e0 = blockIdx.z * 32;
    const int kc0 = ch * KCH;
    const int ty = tid >> 3;          // 0..15
    const int tx = tid & 7;           // 0..7
    const int sa = 4 * (ty & 7);
    const int sb = 4 * (tx & 7);

    ull acc[8][4];
    #pragma unroll
    for (int i = 0; i < 8; i++)
        #pragma unroll
        for (int j = 0; j < 4; j++) acc[i][j] = 0;

    #pragma unroll 1
    for (int t = 0; t < 2; t++) {
        const int kc = kc0 + t * KT;
        __syncthreads();
        {   // stage sZ: 128 x 32 floats, float4 copies + XOR swizzle
            int sm = tid >> 2, q = tid & 3;
            #pragma unroll
            for (int p = 0; p < 4; p++) {
                int m = sm + 32 * p;
                int sw = 4 * ((m >> 3) & 7);
                #pragma unroll
                for (int u = 0; u < 2; u++) {
                    int k4 = q + 4 * u;
                    float4 v = *(const float4*)(z + (size_t)(r0 + m) * D_ + kc + k4 * 4);
                    *(float4*)(&sZ[m][(k4 * 4) ^ sw]) = v;
                }
            }
        }
        {   // stage sE: 32 x 32 floats
            int se = tid >> 2, q = tid & 3;
            int sw = 4 * ((se >> 2) & 7);
            #pragma unroll
            for (int u = 0; u < 2; u++) {
                int k4 = q + 4 * u;
                float4 v = *(const float4*)(g_es + (size_t)(e0 + se) * D_ + kc + k4 * 4);
                *(float4*)(&sE[se][(k4 * 4) ^ sw]) = v;
            }
        }
        __syncthreads();

        #pragma unroll 4
        for (int k = 0; k < KT; k += 2) {
            F2U b[4];
            #pragma unroll
            for (int j = 0; j < 4; j++)
                b[j].f = *(const float2*)(&sE[4 * tx + j][k ^ sb]);
            #pragma unroll
            for (int i = 0; i < 8; i++) {
                F2U a;
                a.f = *(const float2*)(&sZ[8 * ty + i][k ^ sa]);
                #pragma unroll
                for (int j = 0; j < 4; j++)
                    acc[i][j] = fma2(a.u, b[j].u, acc[i][j]);
            }
        }
    }

    // epilogue: horizontal add of even/odd halves, float4 store
    #pragma unroll
    for (int i = 0; i < 8; i++) {
        int m = r0 + 8 * ty + i;
        F2U t0, t1, t2, t3;
        t0.u = acc[i][0]; t1.u = acc[i][1]; t2.u = acc[i][2]; t3.u = acc[i][3];
        float4 v = make_float4(t0.f.x + t0.f.y, t1.f.x + t1.f.y,
                               t2.f.x + t2.f.y, t3.f.x + t3.f.y);
        *(float4*)(g_part + ((size_t)ch * B_ + m) * E_ + e0 + 4 * tx) = v;
    }
}

// ---------------------------------------------------------------------------
// K3: reduce partials + zn + similarity + softmax. warp per row.
// ---------------------------------------------------------------------------
__global__ __launch_bounds__(256) void k3_softmax(const float* __restrict__ z,
                                                  float* __restrict__ out_sim) {
    const int lane = threadIdx.x & 31;
    const int m = blockIdx.x * 8 + (threadIdx.x >> 5);

    float zn = 0.f;
    const float* zr = z + (size_t)m * D_;
    #pragma unroll
    for (int i = 0; i < 8; i++) {
        float4 v = *(const float4*)(zr + lane * 4 + i * 128);
        float4 s = *(const float4*)(g_sinv + lane * 4 + i * 128);
        zn += s.x * v.x * v.x + s.y * v.y * v.y + s.z * v.z * v.z + s.w * v.w * v.w;
    }
    #pragma unroll
    for (int o = 16; o; o >>= 1) zn += __shfl_xor_sync(0xffffffffu, zn, o);

    float dx = 0.f, dy = 0.f;
    #pragma unroll
    for (int c = 0; c < NCHUNK; c++) {
        float2 p = *(const float2*)(g_part + ((size_t)c * B_ + m) * E_ + 2 * lane);
        dx += p.x; dy += p.y;
    }

    float2 en = *(const float2*)(g_en + 2 * lane);
    float sim0 = 1.f / (1.f + zn + en.x - 2.f * dx);
    float sim1 = 1.f / (1.f + zn + en.y - 2.f * dy);
    *(float2*)(out_sim + (size_t)m * E_ + 2 * lane) = make_float2(sim0, sim1);

    float mx = fmaxf(sim0, sim1);
    #pragma unroll
    for (int o = 16; o; o >>= 1) mx = fmaxf(mx, __shfl_xor_sync(0xffffffffu, mx, o));
    float e0 = __expf(sim0 - mx), e1 = __expf(sim1 - mx);
    float s = e0 + e1;
    #pragma unroll
    for (int o = 16; o; o >>= 1) s += __shfl_xor_sync(0xffffffffu, s, o);
    float inv = 1.f / s;
    *(float2*)(g_w + (size_t)m * E_ + 2 * lane) = make_float2(e0 * inv, e1 * inv);
}

// ---------------------------------------------------------------------------
// K4: out_w = W @ ek, e-paired f32x2 accumulators (no dup).
// grid (D/32, B/128). CTA: 128m x 32d x K=64. 128 threads, 8m x 4d each.
// ---------------------------------------------------------------------------
__global__ __launch_bounds__(128, 4) void k4_out(float* __restrict__ out_w) {
    __shared__ __align__(16) float sW[128][E_];  // [m][e] swizzled by 4*((m>>3)&7)
    __shared__ __align__(16) float sB[32][E_];   // [d][e] swizzled by 4*((d>>2)&7)

    const int tid = threadIdx.x;
    const int dc = blockIdx.x * 32;
    const int r0 = blockIdx.y * 128;
    const int ty = tid >> 3;
    const int tx = tid & 7;
    const int sa = 4 * (ty & 7);
    const int sb = 4 * (tx & 7);

    {   // stage sW: 128 rows x 64 floats
        int mhalf = tid >> 1, h = tid & 1;
        #pragma unroll
        for (int p = 0; p < 2; p++) {
            int m = mhalf + 64 * p;
            int sw = 4 * ((m >> 3) & 7);
            #pragma unroll
            for (int u = 0; u < 8; u++) {
                int e4 = h * 8 + u;
                float4 v = *(const float4*)(g_w + (size_t)(r0 + m) * E_ + e4 * 4);
                *(float4*)(&sW[m][(e4 * 4) ^ sw]) = v;
            }
        }
    }
    {   // stage sB from g_ekT rows: 32 x 64 floats
        int d = tid >> 2, q = tid & 3;
        int sw = 4 * ((d >> 2) & 7);
        #pragma unroll
        for (int u = 0; u < 4; u++) {
            int e4 = q + 4 * u;
            float4 v = *(const float4*)(g_ekT + (size_t)(dc + d) * E_ + e4 * 4);
            *(float4*)(&sB[d][(e4 * 4) ^ sw]) = v;
        }
    }
    __syncthreads();

    ull acc[8][4];
    #pragma unroll
    for (int i = 0; i < 8; i++)
        #pragma unroll
        for (int j = 0; j < 4; j++) acc[i][j] = 0;

    #pragma unroll 4
    for (int e = 0; e < E_; e += 2) {
        F2U b[4];
        #pragma unroll
        for (int j = 0; j < 4; j++)
            b[j].f = *(const float2*)(&sB[4 * tx + j][e ^ sb]);
        #pragma unroll
        for (int i = 0; i < 8; i++) {
            F2U a;
            a.f = *(const float2*)(&sW[8 * ty + i][e ^ sa]);
            #pragma unroll
            for (int j = 0; j < 4; j++)
                acc[i][j] = fma2(a.u, b[j].u, acc[i][j]);
        }
    }

    #pragma unroll
    for (int i = 0; i < 8; i++) {
        int m = r0 + 8 * ty + i;
        F2U t0, t1, t2, t3;
        t0.u = acc[i][0]; t1.u = acc[i][1]; t2.u = acc[i][2]; t3.u = acc[i][3];
        float4 v = make_float4(t0.f.x + t0.f.y, t1.f.x + t1.f.y,
                               t2.f.x + t2.f.y, t3.f.x + t3.f.y);
        *(float4*)(out_w + (size_t)m * D_ + dc + 4 * tx) = v;
    }
}

// ---------------------------------------------------------------------------
extern "C" void kernel_launch(void* const* d_in, const int* in_sizes, int n_in,
                              void* d_out, int out_size) {
    const float* z  = (const float*)d_in[0];   // [B, D]
    const float* ek = (const float*)d_in[1];   // [E, D]
    const float* ls = (const float*)d_in[2];   // [D]
    float* out = (float*)d_out;
    float* out_sim = out;                      // [B, E]
    float* out_w   = out + (size_t)B_ * E_;    // [B, D]

    prep_kernel<<<E_, 256>>>(ek, ls);
    k2_dist<<<dim3(NCHUNK, B_ / 128, 2), 128>>>(z);
    k3_softmax<<<B_ / 8, 256>>>(z, out_sim);
    k4_out<<<dim3(D_ / 32, B_ / 128), 128>>>(out_w);
}

// round 6
// speedup vs baseline: 1.6391x; 1.1095x over previous
#include <cuda_runtime.h>
#include <math.h>

#define B_     4096
#define E_     64
#define D_     1024
#define NCHUNK 16
#define KCH    64

typedef unsigned long long ull;
union F2U { ull u; float2 f; };

// -------- scratch (__device__ globals; no allocs allowed) --------
__device__ float g_sinv[D_];
__device__ float g_es[E_ * D_];            // [e][d] = sinv[d]*ek[e][d]
__device__ float g_ekT[D_ * E_];           // [d][e] = ek[e][d]
__device__ float g_en[E_];                 // sum_d sinv*ek^2
__device__ float g_part[NCHUNK * B_ * E_]; // partial dots (16 MB)
__device__ float g_w[B_ * E_];             // softmax weights

static __device__ __forceinline__ ull fma2(ull a, ull b, ull c) {
    ull d;
    asm("fma.rn.f32x2 %0, %1, %2, %3;" : "=l"(d) : "l"(a), "l"(b), "l"(c));
    return d;
}
static __device__ __forceinline__ float hadd(ull v) {
    F2U t; t.u = v; return t.f.x + t.f.y;
}

// ---------------------------------------------------------------------------
// K1: prep — sigma_inv, scaled experts (row-major), transposed ek, norms
// ---------------------------------------------------------------------------
__global__ __launch_bounds__(256) void prep_kernel(const float* __restrict__ ek,
                                                   const float* __restrict__ ls) {
    int e = blockIdx.x;
    int tid = threadIdx.x;
    float acc = 0.f;
    for (int d = tid; d < D_; d += 256) {
        float s = __expf(-ls[d]);
        if (e == 0) g_sinv[d] = s;
        float v = ek[e * D_ + d];
        float sv = s * v;
        g_es[e * D_ + d] = sv;
        g_ekT[d * E_ + e] = v;
        acc += sv * v;
    }
    __shared__ float red[8];
    #pragma unroll
    for (int o = 16; o > 0; o >>= 1) acc += __shfl_down_sync(0xffffffffu, acc, o);
    if ((tid & 31) == 0) red[tid >> 5] = acc;
    __syncthreads();
    if (tid == 0) {
        float s = 0.f;
        #pragma unroll
        for (int i = 0; i < 8; i++) s += red[i];
        g_en[e] = s;
    }
}

// ---------------------------------------------------------------------------
// K2: dist partial GEMM. grid (NCHUNK, B/128), 128 threads.
// CTA tile: 128m x 64e x 64k. Thread tile: 8m x 8e, f32x2 acc paired on k.
// smem 48KB: sZ 128x64 + sE 64x64, XOR-4 swizzle on (row>>3)&7.
// ---------------------------------------------------------------------------
__global__ __launch_bounds__(128, 2) void k2_dist(const float* __restrict__ z) {
    __shared__ __align__(16) float sZ[128 * 64];
    __shared__ __align__(16) float sE[64 * 64];

    const int tid = threadIdx.x;
    const int ch = blockIdx.x;
    const int kc = ch * KCH;
    const int r0 = blockIdx.y * 128;
    const int ty = tid >> 3;            // 0..15 (m-oct)
    const int tx = tid & 7;             // 0..7  (e-oct)
    const int swA = 4 * (ty & 7);
    const int swB = 4 * tx;

    {   // stage sZ: 128 rows x 16 float4
        int r = tid >> 2;
        int c0 = tid & 3;
        #pragma unroll
        for (int p = 0; p < 4; p++) {
            int row = r + 32 * p;
            int sw = 4 * ((row >> 3) & 7);
            const float* src = z + (size_t)(r0 + row) * D_ + kc;
            #pragma unroll
            for (int u = 0; u < 4; u++) {
                int c4 = c0 + 4 * u;
                float4 v = *(const float4*)(src + c4 * 4);
                *(float4*)(&sZ[row * 64 + ((c4 * 4) ^ sw)]) = v;
            }
        }
    }
    {   // stage sE: 64 rows x 16 float4
        int r = tid >> 1;
        int c0 = (tid & 1) * 8;
        int sw = 4 * ((r >> 3) & 7);
        const float* src = g_es + (size_t)r * D_ + kc;
        #pragma unroll
        for (int u = 0; u < 8; u++) {
            int c4 = c0 + u;
            float4 v = *(const float4*)(src + c4 * 4);
            *(float4*)(&sE[r * 64 + ((c4 * 4) ^ sw)]) = v;
        }
    }
    __syncthreads();

    ull acc[8][8];
    #pragma unroll
    for (int i = 0; i < 8; i++)
        #pragma unroll
        for (int j = 0; j < 8; j++) acc[i][j] = 0;

    #pragma unroll 2
    for (int k = 0; k < KCH; k += 2) {
        F2U a[8], b[8];
        #pragma unroll
        for (int j = 0; j < 8; j++)
            b[j].f = *(const float2*)(&sE[(8 * tx + j) * 64 + (k ^ swB)]);
        #pragma unroll
        for (int i = 0; i < 8; i++)
            a[i].f = *(const float2*)(&sZ[(8 * ty + i) * 64 + (k ^ swA)]);
        #pragma unroll
        for (int i = 0; i < 8; i++)
            #pragma unroll
            for (int j = 0; j < 8; j++)
                acc[i][j] = fma2(a[i].u, b[j].u, acc[i][j]);
    }

    #pragma unroll
    for (int i = 0; i < 8; i++) {
        int m = r0 + 8 * ty + i;
        float4 v0 = make_float4(hadd(acc[i][0]), hadd(acc[i][1]),
                                hadd(acc[i][2]), hadd(acc[i][3]));
        float4 v1 = make_float4(hadd(acc[i][4]), hadd(acc[i][5]),
                                hadd(acc[i][6]), hadd(acc[i][7]));
        float* dst = g_part + ((size_t)ch * B_ + m) * E_ + 8 * tx;
        *(float4*)(dst)     = v0;
        *(float4*)(dst + 4) = v1;
    }
}

// ---------------------------------------------------------------------------
// K3: reduce partials + zn + similarity + softmax. warp per row.
// ---------------------------------------------------------------------------
__global__ __launch_bounds__(256) void k3_softmax(const float* __restrict__ z,
                                                  float* __restrict__ out_sim) {
    const int lane = threadIdx.x & 31;
    const int m = blockIdx.x * 8 + (threadIdx.x >> 5);

    float zn = 0.f;
    const float* zr = z + (size_t)m * D_;
    #pragma unroll
    for (int i = 0; i < 8; i++) {
        float4 v = *(const float4*)(zr + lane * 4 + i * 128);
        float4 s = *(const float4*)(g_sinv + lane * 4 + i * 128);
        zn += s.x * v.x * v.x + s.y * v.y * v.y + s.z * v.z * v.z + s.w * v.w * v.w;
    }
    #pragma unroll
    for (int o = 16; o; o >>= 1) zn += __shfl_xor_sync(0xffffffffu, zn, o);

    float dx = 0.f, dy = 0.f;
    #pragma unroll
    for (int c = 0; c < NCHUNK; c++) {
        float2 p = *(const float2*)(g_part + ((size_t)c * B_ + m) * E_ + 2 * lane);
        dx += p.x; dy += p.y;
    }

    float2 en = *(const float2*)(g_en + 2 * lane);
    float sim0 = 1.f / (1.f + zn + en.x - 2.f * dx);
    float sim1 = 1.f / (1.f + zn + en.y - 2.f * dy);
    *(float2*)(out_sim + (size_t)m * E_ + 2 * lane) = make_float2(sim0, sim1);

    float mx = fmaxf(sim0, sim1);
    #pragma unroll
    for (int o = 16; o; o >>= 1) mx = fmaxf(mx, __shfl_xor_sync(0xffffffffu, mx, o));
    float e0 = __expf(sim0 - mx), e1 = __expf(sim1 - mx);
    float s = e0 + e1;
    #pragma unroll
    for (int o = 16; o; o >>= 1) s += __shfl_xor_sync(0xffffffffu, s, o);
    float inv = 1.f / s;
    *(float2*)(g_w + (size_t)m * E_ + 2 * lane) = make_float2(e0 * inv, e1 * inv);
}

// ---------------------------------------------------------------------------
// K4: out_w = W @ ek. grid (D/64, B/128), 128 threads.
// CTA tile: 128m x 64d, K=E=64. Thread tile: 8m x 8d, f32x2 acc paired on e.
// smem 48KB: sW 128x64 + sBT 64x64, same swizzle.
// ---------------------------------------------------------------------------
__global__ __launch_bounds__(128, 2) void k4_out(float* __restrict__ out_w) {
    __shared__ __align__(16) float sW[128 * 64];
    __shared__ __align__(16) float sBT[64 * 64];

    const int tid = threadIdx.x;
    const int dc = blockIdx.x * 64;
    const int r0 = blockIdx.y * 128;
    const int ty = tid >> 3;            // m-oct
    const int tx = tid & 7;             // d-oct
    const int swA = 4 * (ty & 7);
    const int swB = 4 * tx;

    {   // stage sW: 128 rows x 16 float4 from g_w
        int r = tid >> 2;
        int c0 = tid & 3;
        #pragma unroll
        for (int p = 0; p < 4; p++) {
            int row = r + 32 * p;
            int sw = 4 * ((row >> 3) & 7);
            const float* src = g_w + (size_t)(r0 + row) * E_;
            #pragma unroll
            for (int u = 0; u < 4; u++) {
                int c4 = c0 + 4 * u;
                float4 v = *(const float4*)(src + c4 * 4);
                *(float4*)(&sW[row * 64 + ((c4 * 4) ^ sw)]) = v;
            }
        }
    }
    {   // stage sBT: 64 rows x 16 float4 from g_ekT
        int r = tid >> 1;
        int c0 = (tid & 1) * 8;
        int sw = 4 * ((r >> 3) & 7);
        const float* src = g_ekT + (size_t)(dc + r) * E_;
        #pragma unroll
        for (int u = 0; u < 8; u++) {
            int c4 = c0 + u;
            float4 v = *(const float4*)(src + c4 * 4);
            *(float4*)(&sBT[r * 64 + ((c4 * 4) ^ sw)]) = v;
        }
    }
    __syncthreads();

    ull acc[8][8];
    #pragma unroll
    for (int i = 0; i < 8; i++)
        #pragma unroll
        for (int j = 0; j < 8; j++) acc[i][j] = 0;

    #pragma unroll 2
    for (int e = 0; e < E_; e += 2) {
        F2U a[8], b[8];
        #pragma unroll
        for (int j = 0; j < 8; j++)
            b[j].f = *(const float2*)(&sBT[(8 * tx + j) * 64 + (e ^ swB)]);
        #pragma unroll
        for (int i = 0; i < 8; i++)
            a[i].f = *(const float2*)(&sW[(8 * ty + i) * 64 + (e ^ swA)]);
        #pragma unroll
        for (int i = 0; i < 8; i++)
            #pragma unroll
            for (int j = 0; j < 8; j++)
                acc[i][j] = fma2(a[i].u, b[j].u, acc[i][j]);
    }

    #pragma unroll
    for (int i = 0; i < 8; i++) {
        int m = r0 + 8 * ty + i;
        float4 v0 = make_float4(hadd(acc[i][0]), hadd(acc[i][1]),
                                hadd(acc[i][2]), hadd(acc[i][3]));
        float4 v1 = make_float4(hadd(acc[i][4]), hadd(acc[i][5]),
                                hadd(acc[i][6]), hadd(acc[i][7]));
        float* dst = out_w + (size_t)m * D_ + dc + 8 * tx;
        *(float4*)(dst)     = v0;
        *(float4*)(dst + 4) = v1;
    }
}

// ---------------------------------------------------------------------------
extern "C" void kernel_launch(void* const* d_in, const int* in_sizes, int n_in,
                              void* d_out, int out_size) {
    const float* z  = (const float*)d_in[0];   // [B, D]
    const float* ek = (const float*)d_in[1];   // [E, D]
    const float* ls = (const float*)d_in[2];   // [D]
    float* out = (float*)d_out;
    float* out_sim = out;                      // [B, E]
    float* out_w   = out + (size_t)B_ * E_;    // [B, D]

    prep_kernel<<<E_, 256>>>(ek, ls);
    k2_dist<<<dim3(NCHUNK, B_ / 128), 128>>>(z);
    k3_softmax<<<B_ / 8, 256>>>(z, out_sim);
    k4_out<<<dim3(D_ / 64, B_ / 128), 128>>>(out_w);
}

// round 11
// speedup vs baseline: 2.5122x; 1.5327x over previous
#include <cuda_runtime.h>
#include <cuda_bf16.h>
#include <math.h>

#define B_     4096
#define E_     64
#define D_     1024
#define BKC    64           // k per CTA chunk in k2
#define KSPLIT (D_ / BKC)   // 16

// ---------------- scratch (__device__ globals; no allocs allowed) ----------
__device__ __align__(16) float         g_sinv[D_];
__device__ __align__(16) __nv_bfloat16 g_zb[B_ * D_];     // bf16 z
__device__ __align__(16) __nv_bfloat16 g_esb[E_ * D_];    // bf16 sinv*ek, [e][d]
__device__ __align__(16) __nv_bfloat16 g_ekTb[D_ * E_];   // bf16 ek^T, [d][e]
__device__ __align__(16) __nv_bfloat16 g_wres[B_ * E_];   // bf16 (w - 1/64)
__device__ __align__(16) float         g_en[E_];
__device__ __align__(16) float         g_mean[D_];        // (1/64)*colsum(ek)
__device__ __align__(16) float         g_zn[B_];
__device__ __align__(16) float         g_part[KSPLIT * B_ * E_];

// ---------------- mma.sync helpers (base ISA, compute_103-safe) ------------
static __device__ __forceinline__ void ldsm_x4(unsigned& r0, unsigned& r1,
                                               unsigned& r2, unsigned& r3,
                                               unsigned addr) {
    asm volatile("ldmatrix.sync.aligned.m8n8.x4.shared.b16 {%0,%1,%2,%3}, [%4];"
                 : "=r"(r0), "=r"(r1), "=r"(r2), "=r"(r3) : "r"(addr));
}
static __device__ __forceinline__ void mma_bf16(float& c0, float& c1,
                                                float& c2, float& c3,
                                                unsigned a0, unsigned a1,
                                                unsigned a2, unsigned a3,
                                                unsigned b0, unsigned b1) {
    asm volatile(
        "mma.sync.aligned.m16n8k16.row.col.f32.bf16.bf16.f32 "
        "{%0,%1,%2,%3}, {%4,%5,%6,%7}, {%8,%9}, {%0,%1,%2,%3};"
        : "+f"(c0), "+f"(c1), "+f"(c2), "+f"(c3)
        : "r"(a0), "r"(a1), "r"(a2), "r"(a3), "r"(b0), "r"(b1));
}

// padded smem stride: 72 bf16 = 144 B -> 4-bank row skew, conflict-free LDSM
#define PAD 72

// ---------------------------------------------------------------------------
// prep: sigma_inv, es->bf16 (row-major), ek^T->bf16, expert norms
// ---------------------------------------------------------------------------
__global__ __launch_bounds__(256) void prep_kernel(const float* __restrict__ ek,
                                                   const float* __restrict__ ls) {
    int e = blockIdx.x;
    int tid = threadIdx.x;
    float acc = 0.f;
    for (int d = tid; d < D_; d += 256) {
        float s = __expf(-ls[d]);
        if (e == 0) g_sinv[d] = s;
        float v = ek[e * D_ + d];
        float sv = s * v;
        g_esb[e * D_ + d] = __float2bfloat16(sv);
        g_ekTb[d * E_ + e] = __float2bfloat16(v);
        acc += sv * v;
    }
    __shared__ float red[8];
    #pragma unroll
    for (int o = 16; o > 0; o >>= 1) acc += __shfl_down_sync(0xffffffffu, acc, o);
    if ((tid & 31) == 0) red[tid >> 5] = acc;
    __syncthreads();
    if (tid == 0) {
        float s = 0.f;
        #pragma unroll
        for (int i = 0; i < 8; i++) s += red[i];
        g_en[e] = s;
    }
}

// ---------------------------------------------------------------------------
// meank: g_mean[d] = (1/64) * sum_e ek[e][d]
// ---------------------------------------------------------------------------
__global__ __launch_bounds__(256) void meank(const float* __restrict__ ek) {
    int d = blockIdx.x * 256 + threadIdx.x;
    float acc = 0.f;
    #pragma unroll 8
    for (int e = 0; e < E_; e++) acc += ek[(size_t)e * D_ + d];
    g_mean[d] = acc * 0.015625f;
}

// ---------------------------------------------------------------------------
// zconv: z -> bf16 + zn = sum_d sinv*z^2 (warp per row)
// ---------------------------------------------------------------------------
__global__ __launch_bounds__(256) void zconv(const float* __restrict__ z) {
    int lane = threadIdx.x & 31;
    int m = blockIdx.x * 8 + (threadIdx.x >> 5);
    const float* zr = z + (size_t)m * D_;
    float zn = 0.f;
    #pragma unroll
    for (int i = 0; i < 8; i++) {
        int c4 = lane + 32 * i;
        float4 v = *(const float4*)(zr + 4 * c4);
        float4 s = *(const float4*)(g_sinv + 4 * c4);
        zn += s.x * v.x * v.x + s.y * v.y * v.y + s.z * v.z * v.z + s.w * v.w * v.w;
        __nv_bfloat162 b01 = __floats2bfloat162_rn(v.x, v.y);
        __nv_bfloat162 b23 = __floats2bfloat162_rn(v.z, v.w);
        uint2 pk;
        pk.x = *reinterpret_cast<unsigned*>(&b01);
        pk.y = *reinterpret_cast<unsigned*>(&b23);
        *(uint2*)(g_zb + (size_t)m * D_ + 4 * c4) = pk;
    }
    #pragma unroll
    for (int o = 16; o; o >>= 1) zn += __shfl_xor_sync(0xffffffffu, zn, o);
    if (lane == 0) g_zn[m] = zn;
}

// ---------------------------------------------------------------------------
// k2: dist dot GEMM via mma.sync bf16. grid (B/128, KSPLIT), 256 threads.
// CTA: 128m x 64e x 64k chunk. Warp w: rows 16w..16w+15, all 64 e.
// Static smem: 128*72*2 + 64*72*2 = 27648 B (< 48 KB).
// ---------------------------------------------------------------------------
__global__ __launch_bounds__(256) void k2_mma() {
    __shared__ __align__(16) __nv_bfloat16 sA[128 * PAD];
    __shared__ __align__(16) __nv_bfloat16 sB[64 * PAD];

    const int tid = threadIdx.x;
    const int wid = tid >> 5, lane = tid & 31;
    const int r0 = blockIdx.x * 128;
    const int koff = blockIdx.y * BKC;

    {   // stage A: 128 rows x 8 uint4 (2 threads/row, 4 each)
        int r = tid >> 1, half = tid & 1;
        const __nv_bfloat16* src = g_zb + (size_t)(r0 + r) * D_ + koff;
        #pragma unroll
        for (int u = 0; u < 4; u++) {
            int c16 = half * 4 + u;
            uint4 v = *(const uint4*)(src + c16 * 8);
            *(uint4*)(sA + r * PAD + c16 * 8) = v;
        }
    }
    {   // stage B: 64 rows x 8 uint4 (4 threads/row, 2 each)
        int r = tid >> 2, q = tid & 3;
        const __nv_bfloat16* src = g_esb + (size_t)r * D_ + koff;
        #pragma unroll
        for (int u = 0; u < 2; u++) {
            int c16 = q * 2 + u;
            uint4 v = *(const uint4*)(src + c16 * 8);
            *(uint4*)(sB + r * PAD + c16 * 8) = v;
        }
    }
    __syncthreads();

    const unsigned sA_addr = (unsigned)__cvta_generic_to_shared(sA);
    const unsigned sB_addr = (unsigned)__cvta_generic_to_shared(sB);
    // per-lane ldmatrix source rows (verified vs m16n8k16 frag spec)
    const int l7 = lane & 7;
    const int aRow = wid * 16 + l7 + ((lane >> 3) & 1) * 8;
    const int aKo  = (lane >> 4) * 8;
    const int bNo  = l7 + (lane >> 4) * 8;
    const int bKo  = ((lane >> 3) & 1) * 8;

    float c[8][4];
    #pragma unroll
    for (int j = 0; j < 8; j++)
        #pragma unroll
        for (int q = 0; q < 4; q++) c[j][q] = 0.f;

    #pragma unroll
    for (int k16 = 0; k16 < BKC / 16; k16++) {
        const int k0 = k16 * 16;
        unsigned a0, a1, a2, a3;
        ldsm_x4(a0, a1, a2, a3, sA_addr + (aRow * PAD + k0 + aKo) * 2);
        #pragma unroll
        for (int g = 0; g < 4; g++) {   // n = 16g..16g+15
            unsigned b0, b1, b2, b3;
            ldsm_x4(b0, b1, b2, b3,
                    sB_addr + ((16 * g + bNo) * PAD + k0 + bKo) * 2);
            mma_bf16(c[2*g][0], c[2*g][1], c[2*g][2], c[2*g][3],
                     a0, a1, a2, a3, b0, b1);
            mma_bf16(c[2*g+1][0], c[2*g+1][1], c[2*g+1][2], c[2*g+1][3],
                     a0, a1, a2, a3, b2, b3);
        }
    }

    // epilogue: accum frag layout -> g_part
    const int gr = lane >> 2, tc = (lane & 3) * 2;
    const int mrow = r0 + wid * 16 + gr;
    float* dst = g_part + ((size_t)blockIdx.y * B_ + mrow) * E_;
    #pragma unroll
    for (int j = 0; j < 8; j++) {
        *(float2*)(dst + 8 * j + tc)          = make_float2(c[j][0], c[j][1]);
        *(float2*)(dst + 8 * E_ + 8 * j + tc) = make_float2(c[j][2], c[j][3]);
    }
}

// ---------------------------------------------------------------------------
// k3: reduce split-K partials + similarity + softmax + residual weights
// ---------------------------------------------------------------------------
__global__ __launch_bounds__(256) void k3_softmax(float* __restrict__ out_sim) {
    const int lane = threadIdx.x & 31;
    const int m = blockIdx.x * 8 + (threadIdx.x >> 5);

    float dx = 0.f, dy = 0.f;
    #pragma unroll
    for (int ksp = 0; ksp < KSPLIT; ksp++) {
        float2 pp = *(const float2*)(g_part + ((size_t)ksp * B_ + m) * E_ + 2 * lane);
        dx += pp.x; dy += pp.y;
    }
    float zn = g_zn[m];
    float2 en = *(const float2*)(g_en + 2 * lane);
    float sim0 = 1.f / (1.f + zn + en.x - 2.f * dx);
    float sim1 = 1.f / (1.f + zn + en.y - 2.f * dy);
    *(float2*)(out_sim + (size_t)m * E_ + 2 * lane) = make_float2(sim0, sim1);

    float mx = fmaxf(sim0, sim1);
    #pragma unroll
    for (int o = 16; o; o >>= 1) mx = fmaxf(mx, __shfl_xor_sync(0xffffffffu, mx, o));
    float e0 = __expf(sim0 - mx), e1 = __expf(sim1 - mx);
    float s = e0 + e1;
    #pragma unroll
    for (int o = 16; o; o >>= 1) s += __shfl_xor_sync(0xffffffffu, s, o);
    float inv = 1.f / s;
    float w0 = e0 * inv - 0.015625f;   // exact (Sterbenz)
    float w1 = e1 * inv - 0.015625f;
    __nv_bfloat162 h = __floats2bfloat162_rn(w0, w1);
    *(__nv_bfloat162*)(g_wres + (size_t)m * E_ + 2 * lane) = h;
}

// ---------------------------------------------------------------------------
// k4: out_w = mean + wres @ ek via mma.sync bf16. grid (B/128, D/64).
// CTA: 128m x 64d, K = E = 64.
// ---------------------------------------------------------------------------
__global__ __launch_bounds__(256) void k4_mma(float* __restrict__ out_w) {
    __shared__ __align__(16) __nv_bfloat16 sA[128 * PAD];
    __shared__ __align__(16) __nv_bfloat16 sB[64 * PAD];

    const int tid = threadIdx.x;
    const int wid = tid >> 5, lane = tid & 31;
    const int r0 = blockIdx.x * 128;
    const int dc = blockIdx.y * 64;

    {   // stage A: wres 128 rows x 8 uint4 (2 threads/row, 4 each)
        int r = tid >> 1, half = tid & 1;
        const __nv_bfloat16* src = g_wres + (size_t)(r0 + r) * E_;
        #pragma unroll
        for (int u = 0; u < 4; u++) {
            int c16 = half * 4 + u;
            uint4 v = *(const uint4*)(src + c16 * 8);
            *(uint4*)(sA + r * PAD + c16 * 8) = v;
        }
    }
    {   // stage B: ekT rows dc..dc+63, 8 uint4 each (4 threads/row, 2 each)
        int r = tid >> 2, q = tid & 3;
        const __nv_bfloat16* src = g_ekTb + (size_t)(dc + r) * E_;
        #pragma unroll
        for (int u = 0; u < 2; u++) {
            int c16 = q * 2 + u;
            uint4 v = *(const uint4*)(src + c16 * 8);
            *(uint4*)(sB + r * PAD + c16 * 8) = v;
        }
    }
    __syncthreads();

    const unsigned sA_addr = (unsigned)__cvta_generic_to_shared(sA);
    const unsigned sB_addr = (unsigned)__cvta_generic_to_shared(sB);
    const int l7 = lane & 7;
    const int aRow = wid * 16 + l7 + ((lane >> 3) & 1) * 8;
    const int aKo  = (lane >> 4) * 8;
    const int bNo  = l7 + (lane >> 4) * 8;
    const int bKo  = ((lane >> 3) & 1) * 8;

    float c[8][4];
    #pragma unroll
    for (int j = 0; j < 8; j++)
        #pragma unroll
        for (int q = 0; q < 4; q++) c[j][q] = 0.f;

    #pragma unroll
    for (int k16 = 0; k16 < 4; k16++) {
        const int k0 = k16 * 16;
        unsigned a0, a1, a2, a3;
        ldsm_x4(a0, a1, a2, a3, sA_addr + (aRow * PAD + k0 + aKo) * 2);
        #pragma unroll
        for (int g = 0; g < 4; g++) {
            unsigned b0, b1, b2, b3;
            ldsm_x4(b0, b1, b2, b3,
                    sB_addr + ((16 * g + bNo) * PAD + k0 + bKo) * 2);
            mma_bf16(c[2*g][0], c[2*g][1], c[2*g][2], c[2*g][3],
                     a0, a1, a2, a3, b0, b1);
            mma_bf16(c[2*g+1][0], c[2*g+1][1], c[2*g+1][2], c[2*g+1][3],
                     a0, a1, a2, a3, b2, b3);
        }
    }

    // epilogue: add mean, write out
    const int gr = lane >> 2, tc = (lane & 3) * 2;
    const int mrow = r0 + wid * 16 + gr;
    #pragma unroll
    for (int j = 0; j < 8; j++) {
        float2 mn = *(const float2*)(g_mean + dc + 8 * j + tc);
        *(float2*)(out_w + (size_t)mrow * D_ + dc + 8 * j + tc)
            = make_float2(c[j][0] + mn.x, c[j][1] + mn.y);
        *(float2*)(out_w + (size_t)(mrow + 8) * D_ + dc + 8 * j + tc)
            = make_float2(c[j][2] + mn.x, c[j][3] + mn.y);
    }
}

// ---------------------------------------------------------------------------
extern "C" void kernel_launch(void* const* d_in, const int* in_sizes, int n_in,
                              void* d_out, int out_size) {
    const float* z  = (const float*)d_in[0];   // [B, D]
    const float* ek = (const float*)d_in[1];   // [E, D]
    const float* ls = (const float*)d_in[2];   // [D]
    float* out = (float*)d_out;
    float* out_sim = out;                      // [B, E]
    float* out_w   = out + (size_t)B_ * E_;    // [B, D]

    prep_kernel<<<E_, 256>>>(ek, ls);
    meank<<<D_ / 256, 256>>>(ek);
    zconv<<<B_ / 8, 256>>>(z);
    k2_mma<<<dim3(B_ / 128, KSPLIT), 256>>>();
    k3_softmax<<<B_ / 8, 256>>>(out_sim);
    k4_mma<<<dim3(B_ / 128, D_ / 64), 256>>>(out_w);
}